// round 8
// baseline (speedup 1.0000x reference)
#include <cuda_runtime.h>
#include <cuda_bf16.h>
#include <mma.h>
#include <cstdint>
#include <cstddef>

using namespace nvcuda;

// ---------------------------------------------------------------------------
// Fixed shapes: N=100000, E=1600000, F 128 -> 128 -> 64
// ---------------------------------------------------------------------------
#define MAX_N 100000
#define MAX_E 1600000
#define SCAN_CHUNK 1024
#define MAX_CHUNKS ((MAX_N + SCAN_CHUNK - 1) / SCAN_CHUNK)   // 98

// Scratch (device BSS — no allocation inside kernel_launch)
__device__ float g_buf [(size_t)MAX_N * 128];   // x @ W1
__device__ float h_buf [(size_t)MAX_N * 128];   // relu+bias+dropout(spmm1)
__device__ float p_buf [(size_t)MAX_N * 64];    // h @ W2

__device__ int   deg_buf   [MAX_N];
__device__ int   row_ptr   [MAX_N + 1];
__device__ int   cursor    [MAX_N];
__device__ int   part_buf  [MAX_CHUNKS];
__device__ int   partoff   [MAX_CHUNKS];
__device__ int   src_sorted[MAX_E];
__device__ float w_sorted  [MAX_E];

// bf16 hi/lo split of W1, row-major [k][n] (same layout as W1)
__device__ __align__(16) __nv_bfloat16 w1_hi[128 * 128];
__device__ __align__(16) __nv_bfloat16 w1_lo[128 * 128];

// ---------------------------------------------------------------------------
// Threefry-2x32, key = (0, 42) — bit-exact replica of jax threefry2x32 core
// ---------------------------------------------------------------------------
__device__ __forceinline__ void threefry_0_42(uint32_t x0, uint32_t x1,
                                              uint32_t& o0, uint32_t& o1)
{
    const uint32_t k0 = 0u, k1 = 42u;
    const uint32_t k2 = k0 ^ k1 ^ 0x1BD11BDAu;
    x0 += k0; x1 += k1;
#define TF_R(r) { x0 += x1; x1 = (x1 << (r)) | (x1 >> (32 - (r))); x1 ^= x0; }
    TF_R(13) TF_R(15) TF_R(26) TF_R(6)   x0 += k1; x1 += k2 + 1u;
    TF_R(17) TF_R(29) TF_R(16) TF_R(24)  x0 += k2; x1 += k0 + 2u;
    TF_R(13) TF_R(15) TF_R(26) TF_R(6)   x0 += k0; x1 += k1 + 3u;
    TF_R(17) TF_R(29) TF_R(16) TF_R(24)  x0 += k1; x1 += k2 + 4u;
    TF_R(13) TF_R(15) TF_R(26) TF_R(6)   x0 += k2; x1 += k0 + 5u;
#undef TF_R
    o0 = x0; o1 = x1;
}

__device__ __forceinline__ bool drop_mask(uint32_t i)
{
    uint32_t o0, o1;
    threefry_0_42(0u, i, o0, o1);
    return ((o0 ^ o1) & 0x80000000u) != 0u;   // true = drop (XOR-fold)
}

// ---------------------------------------------------------------------------
// Packed fp32x2 FMA helpers (FFMA2) — used by gemm2
// ---------------------------------------------------------------------------
#define FMA2(acc_, a_, b_) \
    asm("fma.rn.f32x2 %0, %1, %2, %0;" : "+l"(acc_) : "l"(a_), "l"(b_))

__device__ __forceinline__ unsigned long long dup2(float a)
{
    unsigned long long r;
    asm("mov.b64 %0, {%1, %1};" : "=l"(r) : "r"(__float_as_uint(a)));
    return r;
}

// ===========================================================================
// Prep: split W1 (fp32 row-major [k][n]) into bf16 hi/lo, same layout.
// ===========================================================================
__global__ void k_prep_w1(const float* __restrict__ W1)
{
    const int idx = blockIdx.x * blockDim.x + threadIdx.x;
    if (idx >= 128 * 128) return;
    const float w = W1[idx];
    const __nv_bfloat16 hi = __float2bfloat16(w);
    const __nv_bfloat16 lo = __float2bfloat16(w - __bfloat162float(hi));
    w1_hi[idx] = hi;
    w1_lo[idx] = lo;
}

// ===========================================================================
// gemm1 (wmma bf16, 3-pass EFT split): g = x @ W1
//   pass 0: Ahi @ Bhi,  pass 1: Ahi @ Blo,  pass 2: Alo @ Bhi
// CTA = 128 rows x 128 cols, 256 threads = 8 warps (2x4 warp grid).
// Each warp: 64x32 output = 4x2 fragments of 16x16, fp32 accumulate.
// A tile converted once to SMEM bf16 hi/lo (LDA=136 to avoid conflicts).
// ===========================================================================
#define G1_LDA 136
#define G1_SMEM_BYTES (2 * 128 * G1_LDA * 2)   // 69632

__global__ void __launch_bounds__(256, 2)
gemm1_wmma(const float* __restrict__ x, int M)
{
    extern __shared__ __align__(16) __nv_bfloat16 smem_bf[];
    __nv_bfloat16* Ahi = smem_bf;
    __nv_bfloat16* Alo = smem_bf + 128 * G1_LDA;

    const int tid = threadIdx.x;
    const int wid = tid >> 5;
    const int m0  = blockIdx.x * 128;
    const int warp_m = wid >> 2;   // 0..1
    const int warp_n = wid & 3;    // 0..3

    // Convert A tile (128x128 fp32) -> SMEM bf16 hi/lo
    for (int i = tid; i < 128 * 32; i += 256) {      // i indexes float4s
        const int row = i >> 5;
        const int c4  = (i & 31) * 4;
        int grow = m0 + row;
        if (grow > M - 1) grow = M - 1;              // clamp; never stored
        const float4 v = __ldg((const float4*)(x + (size_t)grow * 128 + c4));
        __nv_bfloat16 h0 = __float2bfloat16(v.x);
        __nv_bfloat16 h1 = __float2bfloat16(v.y);
        __nv_bfloat16 h2 = __float2bfloat16(v.z);
        __nv_bfloat16 h3 = __float2bfloat16(v.w);
        __nv_bfloat16* ph = Ahi + row * G1_LDA + c4;
        __nv_bfloat16* pl = Alo + row * G1_LDA + c4;
        ph[0] = h0; ph[1] = h1; ph[2] = h2; ph[3] = h3;
        pl[0] = __float2bfloat16(v.x - __bfloat162float(h0));
        pl[1] = __float2bfloat16(v.y - __bfloat162float(h1));
        pl[2] = __float2bfloat16(v.z - __bfloat162float(h2));
        pl[3] = __float2bfloat16(v.w - __bfloat162float(h3));
    }
    __syncthreads();

    wmma::fragment<wmma::accumulator, 16, 16, 16, float> acc[4][2];
#pragma unroll
    for (int mf = 0; mf < 4; mf++)
#pragma unroll
        for (int nf = 0; nf < 2; nf++)
            wmma::fill_fragment(acc[mf][nf], 0.0f);

#pragma unroll
    for (int pass = 0; pass < 3; pass++) {
        const __nv_bfloat16* As   = (pass == 2) ? Alo : Ahi;
        const __nv_bfloat16* Bimg = (pass == 1) ? w1_lo : w1_hi;
#pragma unroll
        for (int ks = 0; ks < 8; ks++) {
            wmma::fragment<wmma::matrix_b, 16, 16, 16, __nv_bfloat16,
                           wmma::row_major> bf[2];
#pragma unroll
            for (int nf = 0; nf < 2; nf++)
                wmma::load_matrix_sync(
                    bf[nf], Bimg + ks * 16 * 128 + warp_n * 32 + nf * 16, 128);
#pragma unroll
            for (int mf = 0; mf < 4; mf++) {
                wmma::fragment<wmma::matrix_a, 16, 16, 16, __nv_bfloat16,
                               wmma::row_major> af;
                wmma::load_matrix_sync(
                    af, As + (warp_m * 64 + mf * 16) * G1_LDA + ks * 16, G1_LDA);
#pragma unroll
                for (int nf = 0; nf < 2; nf++)
                    wmma::mma_sync(acc[mf][nf], af, bf[nf], acc[mf][nf]);
            }
        }
    }

    // Store (M % 16 == 0, so fragments are fully valid or fully invalid)
#pragma unroll
    for (int mf = 0; mf < 4; mf++) {
        const int r0 = m0 + warp_m * 64 + mf * 16;
        if (r0 + 16 <= M) {
#pragma unroll
            for (int nf = 0; nf < 2; nf++)
                wmma::store_matrix_sync(
                    g_buf + (size_t)r0 * 128 + warp_n * 32 + nf * 16,
                    acc[mf][nf], 128, wmma::mem_row_major);
        }
    }
}

// ===========================================================================
// CSR build: deg -> scan -> scatter   (unchanged, certified)
// ===========================================================================
__global__ void k_zero_deg(int N)
{
    const int i = blockIdx.x * blockDim.x + threadIdx.x;
    if (i < N) deg_buf[i] = 0;
}

__global__ void k_hist(const int* __restrict__ dst, int E)
{
    const int e = blockIdx.x * blockDim.x + threadIdx.x;
    if (e < E) atomicAdd(&deg_buf[dst[e]], 1);
}

__global__ void k_part_sums(int N)
{
    __shared__ int sm[256];
    const int b = blockIdx.x, t = threadIdx.x;
    int s = 0;
#pragma unroll
    for (int k = 0; k < 4; k++) {
        const int i = b * SCAN_CHUNK + k * 256 + t;
        if (i < N) s += deg_buf[i];
    }
    sm[t] = s; __syncthreads();
    for (int off = 128; off > 0; off >>= 1) {
        if (t < off) sm[t] += sm[t + off];
        __syncthreads();
    }
    if (t == 0) part_buf[b] = sm[0];
}

__global__ void k_scan_parts(int nchunks, int N, int E)
{
    __shared__ int sm[128];
    const int t = threadIdx.x;
    const int v = (t < nchunks) ? part_buf[t] : 0;
    sm[t] = v; __syncthreads();
#pragma unroll
    for (int off = 1; off < 128; off <<= 1) {
        const int x = (t >= off) ? sm[t - off] : 0;
        __syncthreads();
        sm[t] += x;
        __syncthreads();
    }
    if (t < nchunks) partoff[t] = sm[t] - v;
    if (t == 0) row_ptr[N] = E;
}

__global__ void k_scan_chunks(int N)
{
    __shared__ int sm[SCAN_CHUNK];
    const int b = blockIdx.x, t = threadIdx.x;
    const int i = b * SCAN_CHUNK + t;
    const int v = (i < N) ? deg_buf[i] : 0;
    sm[t] = v; __syncthreads();
#pragma unroll
    for (int off = 1; off < SCAN_CHUNK; off <<= 1) {
        const int x = (t >= off) ? sm[t - off] : 0;
        __syncthreads();
        sm[t] += x;
        __syncthreads();
    }
    if (i < N) {
        const int ex = sm[t] - v + partoff[b];
        row_ptr[i] = ex;
        cursor[i]  = ex;
    }
}

__global__ void k_scatter(const int* __restrict__ src, const int* __restrict__ dst,
                          const float* __restrict__ ew, int E)
{
    const int e = blockIdx.x * blockDim.x + threadIdx.x;
    if (e >= E) return;
    const int pos = atomicAdd(&cursor[dst[e]], 1);
    src_sorted[pos] = src[e];
    w_sorted[pos]   = ew[e];
}

// ===========================================================================
// gemm2 (FFMA2): p = h @ W2   (BN=64, K=128) — unchanged, certified
// ===========================================================================
__global__ void __launch_bounds__(256, 2)
gemm2_k128(const float* __restrict__ B, int M)
{
    constexpr int BN = 64;
    const float* __restrict__ A = h_buf;
    float* __restrict__ C       = p_buf;

    __shared__ __align__(16) float As[2][16 * 128];
    __shared__ __align__(16) float Bs[2][16 * BN];

    const int tid = threadIdx.x;
    const int tx  = tid & 15;
    const int ty  = tid >> 4;
    const int m0  = blockIdx.x * 128;
    const int lr  = tid >> 2;
    const int lc  = tid & 3;

    unsigned long long acc[8][2];
#pragma unroll
    for (int r = 0; r < 8; r++) { acc[r][0] = 0ull; acc[r][1] = 0ull; }

    auto loadTiles = [&](int buf, int kk) {
#pragma unroll
        for (int rr = 0; rr < 2; rr++) {
            int row = m0 + lr + rr * 64;
            if (row > M - 1) row = M - 1;
            const float4 v = *(const float4*)(A + (size_t)row * 128 + kk + lc * 4);
            float* d = &As[buf][0];
            const int mi = lr + rr * 64;
            d[(lc * 4 + 0) * 128 + mi] = v.x;
            d[(lc * 4 + 1) * 128 + mi] = v.y;
            d[(lc * 4 + 2) * 128 + mi] = v.z;
            d[(lc * 4 + 3) * 128 + mi] = v.w;
        }
        {
            const int idx = tid * 4;
            if (idx < 16 * BN)
                *(float4*)&Bs[buf][idx] = *(const float4*)(B + kk * BN + idx);
        }
    };

    loadTiles(0, 0);
    __syncthreads();

#pragma unroll 1
    for (int kk = 0; kk < 128; kk += 16) {
        const int cur = (kk >> 4) & 1;
        if (kk + 16 < 128) loadTiles(cur ^ 1, kk + 16);
#pragma unroll
        for (int k = 0; k < 16; k++) {
            const float4 a0 = *(const float4*)&As[cur][k * 128 + ty * 4];
            const float4 a1 = *(const float4*)&As[cur][k * 128 + ty * 4 + 64];
            unsigned long long a2[8];
            a2[0] = dup2(a0.x); a2[1] = dup2(a0.y);
            a2[2] = dup2(a0.z); a2[3] = dup2(a0.w);
            a2[4] = dup2(a1.x); a2[5] = dup2(a1.y);
            a2[6] = dup2(a1.z); a2[7] = dup2(a1.w);
            const double2 b = *(const double2*)&Bs[cur][k * BN + tx * 4];
            const unsigned long long bl = __double_as_longlong(b.x);
            const unsigned long long bh = __double_as_longlong(b.y);
#pragma unroll
            for (int r = 0; r < 8; r++) {
                FMA2(acc[r][0], a2[r], bl);
                FMA2(acc[r][1], a2[r], bh);
            }
        }
        __syncthreads();
    }

#pragma unroll
    for (int r = 0; r < 8; r++) {
        const int row = m0 + ty * 4 + (r >> 2) * 64 + (r & 3);
        if (row < M) {
            const unsigned long long v0 = acc[r][0];
            const unsigned long long v1 = acc[r][1];
            float4 o;
            o.x = __uint_as_float((unsigned)(v0 & 0xffffffffu));
            o.y = __uint_as_float((unsigned)(v0 >> 32));
            o.z = __uint_as_float((unsigned)(v1 & 0xffffffffu));
            o.w = __uint_as_float((unsigned)(v1 >> 32));
            *(float4*)(C + (size_t)row * BN + tx * 4) = o;
        }
    }
}

// ===========================================================================
// SpMM1 (CSR, F=128) fused with bias+relu+dropout epilogue — unchanged
// ===========================================================================
__global__ void __launch_bounds__(256)
spmm1_fused(const float* __restrict__ b1, int N)
{
    const int d    = (blockIdx.x * blockDim.x + threadIdx.x) >> 5;
    const int lane = threadIdx.x & 31;
    if (d >= N) return;

    const int beg = row_ptr[d];
    const int end = row_ptr[d + 1];

    float4 acc = make_float4(0.f, 0.f, 0.f, 0.f);
    const float* __restrict__ G = g_buf;

    int j = beg;
    for (; j + 4 <= end; j += 4) {
        const int   s0 = src_sorted[j],     s1 = src_sorted[j + 1];
        const int   s2 = src_sorted[j + 2], s3 = src_sorted[j + 3];
        const float w0 = w_sorted[j],       w1 = w_sorted[j + 1];
        const float w2 = w_sorted[j + 2],   w3 = w_sorted[j + 3];
        const float4 v0 = *(const float4*)(G + (size_t)s0 * 128 + lane * 4);
        const float4 v1 = *(const float4*)(G + (size_t)s1 * 128 + lane * 4);
        const float4 v2 = *(const float4*)(G + (size_t)s2 * 128 + lane * 4);
        const float4 v3 = *(const float4*)(G + (size_t)s3 * 128 + lane * 4);
        acc.x += w0 * v0.x + w1 * v1.x + w2 * v2.x + w3 * v3.x;
        acc.y += w0 * v0.y + w1 * v1.y + w2 * v2.y + w3 * v3.y;
        acc.z += w0 * v0.z + w1 * v1.z + w2 * v2.z + w3 * v3.z;
        acc.w += w0 * v0.w + w1 * v1.w + w2 * v2.w + w3 * v3.w;
    }
    for (; j < end; j++) {
        const int   s = src_sorted[j];
        const float w = w_sorted[j];
        const float4 v = *(const float4*)(G + (size_t)s * 128 + lane * 4);
        acc.x += w * v.x; acc.y += w * v.y; acc.z += w * v.z; acc.w += w * v.w;
    }

    const float4 bv = *(const float4*)(b1 + lane * 4);
    const uint32_t base = (uint32_t)d * 128u + (uint32_t)lane * 4u;

    float4 o;
    float v0 = fmaxf(acc.x + bv.x, 0.f);
    float v1 = fmaxf(acc.y + bv.y, 0.f);
    float v2 = fmaxf(acc.z + bv.z, 0.f);
    float v3 = fmaxf(acc.w + bv.w, 0.f);
    o.x = drop_mask(base + 0u) ? 0.f : v0 * 2.f;
    o.y = drop_mask(base + 1u) ? 0.f : v1 * 2.f;
    o.z = drop_mask(base + 2u) ? 0.f : v2 * 2.f;
    o.w = drop_mask(base + 3u) ? 0.f : v3 * 2.f;
    *(float4*)(h_buf + (size_t)d * 128 + lane * 4) = o;
}

// ===========================================================================
// SpMM2 (CSR, F=64) fused with +b2 — unchanged
// ===========================================================================
__global__ void __launch_bounds__(256)
spmm2_fused(const float* __restrict__ b2, float* __restrict__ out, int N)
{
    const int d    = (blockIdx.x * blockDim.x + threadIdx.x) >> 5;
    const int lane = threadIdx.x & 31;
    if (d >= N) return;

    const int beg = row_ptr[d];
    const int end = row_ptr[d + 1];

    float2 acc = make_float2(0.f, 0.f);
    const float* __restrict__ P = p_buf;

    int j = beg;
    for (; j + 8 <= end; j += 8) {
        int   s[8]; float w[8]; float2 v[8];
#pragma unroll
        for (int q = 0; q < 8; q++) { s[q] = src_sorted[j + q]; w[q] = w_sorted[j + q]; }
#pragma unroll
        for (int q = 0; q < 8; q++) v[q] = *(const float2*)(P + (size_t)s[q] * 64 + lane * 2);
#pragma unroll
        for (int q = 0; q < 8; q++) { acc.x += w[q] * v[q].x; acc.y += w[q] * v[q].y; }
    }
    for (; j < end; j++) {
        const int   s = src_sorted[j];
        const float w = w_sorted[j];
        const float2 v = *(const float2*)(P + (size_t)s * 64 + lane * 2);
        acc.x += w * v.x; acc.y += w * v.y;
    }

    const float2 bv = *(const float2*)(b2 + lane * 2);
    float2 o; o.x = acc.x + bv.x; o.y = acc.y + bv.y;
    *(float2*)(out + (size_t)d * 64 + lane * 2) = o;
}

// ---------------------------------------------------------------------------
// kernel_launch
// inputs: x, edge_weight, W1, b1, W2, b2, src, dst, n_nodes
// ---------------------------------------------------------------------------
extern "C" void kernel_launch(void* const* d_in, const int* in_sizes, int n_in,
                              void* d_out, int out_size)
{
    const float* x   = (const float*)d_in[0];
    const float* ew  = (const float*)d_in[1];
    const float* W1  = (const float*)d_in[2];
    const float* b1  = (const float*)d_in[3];
    const float* W2  = (const float*)d_in[4];
    const float* b2  = (const float*)d_in[5];
    const int*   src = (const int*)d_in[6];
    const int*   dst = (const int*)d_in[7];

    const int N = in_sizes[0] / 128;
    const int E = in_sizes[1];
    float* out = (float*)d_out;

    const int nchunks = (N + SCAN_CHUNK - 1) / SCAN_CHUNK;

    static cudaStream_t s2 = nullptr;
    static cudaEvent_t  ev_fork = nullptr, ev_join = nullptr;
    static bool tried = false;
    if (!tried) {
        tried = true;
        cudaFuncSetAttribute(gemm1_wmma, cudaFuncAttributeMaxDynamicSharedMemorySize,
                             G1_SMEM_BYTES);
        if (cudaStreamCreateWithFlags(&s2, cudaStreamNonBlocking) != cudaSuccess) s2 = nullptr;
        if (s2) {
            cudaEventCreateWithFlags(&ev_fork, cudaEventDisableTiming);
            cudaEventCreateWithFlags(&ev_join, cudaEventDisableTiming);
        }
    }

    cudaStream_t cs = s2 ? s2 : (cudaStream_t)0;

    if (s2) {
        cudaEventRecord(ev_fork, 0);
        cudaStreamWaitEvent(s2, ev_fork, 0);
    }

    // --- CSR build on secondary stream (independent of gemm1) ---
    k_zero_deg   <<<(N + 255) / 256, 256, 0, cs>>>(N);
    k_hist       <<<(E + 255) / 256, 256, 0, cs>>>(dst, E);
    k_part_sums  <<<nchunks, 256, 0, cs>>>(N);
    k_scan_parts <<<1, 128, 0, cs>>>(nchunks, N, E);
    k_scan_chunks<<<nchunks, SCAN_CHUNK, 0, cs>>>(N);
    k_scatter    <<<(E + 255) / 256, 256, 0, cs>>>(src, dst, ew, E);

    if (s2) cudaEventRecord(ev_join, s2);

    // --- main stream: W1 split + wmma gemm1, overlapped with CSR ---
    k_prep_w1<<<(128 * 128 + 255) / 256, 256>>>(W1);
    gemm1_wmma<<<(N + 127) / 128, 256, G1_SMEM_BYTES>>>(x, N);

    if (s2) cudaStreamWaitEvent((cudaStream_t)0, ev_join, 0);

    // h = relu(spmm(A, g) + b1) * mask * 2
    spmm1_fused<<<(N * 32 + 255) / 256, 256>>>(b1, N);
    // p = h @ W2
    gemm2_k128<<<(N + 127) / 128, 256>>>(W2, N);
    // out = spmm(A, p) + b2
    spmm2_fused<<<(N * 32 + 255) / 256, 256>>>(b2, out, N);
}

// round 9
// speedup vs baseline: 1.2063x; 1.2063x over previous
#include <cuda_runtime.h>
#include <cstdint>
#include <cstddef>

// ---------------------------------------------------------------------------
// Fixed shapes: N=100000, E=1600000, F 128 -> 128 -> 64
// ---------------------------------------------------------------------------
#define MAX_N 100000
#define MAX_E 1600000
#define SCAN_CHUNK 1024
#define MAX_CHUNKS ((MAX_N + SCAN_CHUNK - 1) / SCAN_CHUNK)   // 98

// Scratch (device BSS — no allocation inside kernel_launch)
__device__ float g_buf [(size_t)MAX_N * 128];   // x @ W1
__device__ float h_buf [(size_t)MAX_N * 128];   // relu+bias+dropout(spmm1)
__device__ float p_buf [(size_t)MAX_N * 64];    // h @ W2

__device__ int   deg_buf   [MAX_N];
__device__ int   row_ptr   [MAX_N + 1];
__device__ int   cursor    [MAX_N];
__device__ int   part_buf  [MAX_CHUNKS];
__device__ int   partoff   [MAX_CHUNKS];
__device__ int2  edge_sorted[MAX_E];            // packed (src, w_bits)

// ---------------------------------------------------------------------------
// Threefry-2x32, key = (0, 42) — bit-exact replica of jax threefry2x32 core
// ---------------------------------------------------------------------------
__device__ __forceinline__ void threefry_0_42(uint32_t x0, uint32_t x1,
                                              uint32_t& o0, uint32_t& o1)
{
    const uint32_t k0 = 0u, k1 = 42u;
    const uint32_t k2 = k0 ^ k1 ^ 0x1BD11BDAu;
    x0 += k0; x1 += k1;
#define TF_R(r) { x0 += x1; x1 = (x1 << (r)) | (x1 >> (32 - (r))); x1 ^= x0; }
    TF_R(13) TF_R(15) TF_R(26) TF_R(6)   x0 += k1; x1 += k2 + 1u;
    TF_R(17) TF_R(29) TF_R(16) TF_R(24)  x0 += k2; x1 += k0 + 2u;
    TF_R(13) TF_R(15) TF_R(26) TF_R(6)   x0 += k0; x1 += k1 + 3u;
    TF_R(17) TF_R(29) TF_R(16) TF_R(24)  x0 += k1; x1 += k2 + 4u;
    TF_R(13) TF_R(15) TF_R(26) TF_R(6)   x0 += k2; x1 += k0 + 5u;
#undef TF_R
    o0 = x0; o1 = x1;
}

__device__ __forceinline__ bool drop_mask(uint32_t i)
{
    uint32_t o0, o1;
    threefry_0_42(0u, i, o0, o1);
    return ((o0 ^ o1) & 0x80000000u) != 0u;   // true = drop (XOR-fold)
}

// ---------------------------------------------------------------------------
// Packed fp32x2 FMA helpers (FFMA2)
// ---------------------------------------------------------------------------
#define FMA2(acc_, a_, b_) \
    asm("fma.rn.f32x2 %0, %1, %2, %0;" : "+l"(acc_) : "l"(a_), "l"(b_))

__device__ __forceinline__ unsigned long long dup2(float a)
{
    unsigned long long r;
    asm("mov.b64 %0, {%1, %1};" : "=l"(r) : "r"(__float_as_uint(a)));
    return r;
}

// ===========================================================================
// GEMM:  C[M, BN] = A[M, 128] @ B[128, BN]  (R6-certified FFMA2 version)
// ===========================================================================
template<int BN, bool A_IS_H>
__global__ void __launch_bounds__(256, 2)
gemm_k128(const float* __restrict__ Aarg, const float* __restrict__ B, int M)
{
    const float* __restrict__ A = A_IS_H ? h_buf : Aarg;
    float* __restrict__ C       = A_IS_H ? p_buf : g_buf;

    __shared__ __align__(16) float As[2][16 * 128];
    __shared__ __align__(16) float Bs[2][16 * BN];

    const int tid = threadIdx.x;
    const int tx  = tid & 15;
    const int ty  = tid >> 4;
    const int m0  = blockIdx.x * 128;
    const int lr  = tid >> 2;
    const int lc  = tid & 3;

    constexpr int NG = BN / 64;
    unsigned long long acc[8][2 * NG];
#pragma unroll
    for (int r = 0; r < 8; r++)
#pragma unroll
        for (int j = 0; j < 2 * NG; j++) acc[r][j] = 0ull;

    auto loadTiles = [&](int buf, int kk) {
#pragma unroll
        for (int rr = 0; rr < 2; rr++) {
            int row = m0 + lr + rr * 64;
            if (row > M - 1) row = M - 1;
            const float4 v = *(const float4*)(A + (size_t)row * 128 + kk + lc * 4);
            float* d = &As[buf][0];
            const int mi = lr + rr * 64;
            d[(lc * 4 + 0) * 128 + mi] = v.x;
            d[(lc * 4 + 1) * 128 + mi] = v.y;
            d[(lc * 4 + 2) * 128 + mi] = v.z;
            d[(lc * 4 + 3) * 128 + mi] = v.w;
        }
#pragma unroll
        for (int i = 0; i < (16 * BN) / 1024; i++) {
            const int idx = (i * 256 + tid) * 4;
            *(float4*)&Bs[buf][idx] = *(const float4*)(B + kk * BN + idx);
        }
    };

    loadTiles(0, 0);
    __syncthreads();

#pragma unroll 1
    for (int kk = 0; kk < 128; kk += 16) {
        const int cur = (kk >> 4) & 1;
        if (kk + 16 < 128) loadTiles(cur ^ 1, kk + 16);
#pragma unroll
        for (int k = 0; k < 16; k++) {
            const float4 a0 = *(const float4*)&As[cur][k * 128 + ty * 4];
            const float4 a1 = *(const float4*)&As[cur][k * 128 + ty * 4 + 64];
            unsigned long long a2[8];
            a2[0] = dup2(a0.x); a2[1] = dup2(a0.y);
            a2[2] = dup2(a0.z); a2[3] = dup2(a0.w);
            a2[4] = dup2(a1.x); a2[5] = dup2(a1.y);
            a2[6] = dup2(a1.z); a2[7] = dup2(a1.w);
#pragma unroll
            for (int g = 0; g < NG; g++) {
                const double2 b = *(const double2*)&Bs[cur][k * BN + tx * 4 + g * 64];
                const unsigned long long bl = __double_as_longlong(b.x);
                const unsigned long long bh = __double_as_longlong(b.y);
#pragma unroll
                for (int r = 0; r < 8; r++) {
                    FMA2(acc[r][2 * g + 0], a2[r], bl);
                    FMA2(acc[r][2 * g + 1], a2[r], bh);
                }
            }
        }
        __syncthreads();
    }

#pragma unroll
    for (int r = 0; r < 8; r++) {
        const int row = m0 + ty * 4 + (r >> 2) * 64 + (r & 3);
        if (row < M) {
#pragma unroll
            for (int g = 0; g < NG; g++) {
                const unsigned long long v0 = acc[r][2 * g + 0];
                const unsigned long long v1 = acc[r][2 * g + 1];
                float4 o;
                o.x = __uint_as_float((unsigned)(v0 & 0xffffffffu));
                o.y = __uint_as_float((unsigned)(v0 >> 32));
                o.z = __uint_as_float((unsigned)(v1 & 0xffffffffu));
                o.w = __uint_as_float((unsigned)(v1 >> 32));
                *(float4*)(C + (size_t)row * BN + tx * 4 + g * 64) = o;
            }
        }
    }
}

// ===========================================================================
// CSR build: deg -> scan -> scatter (packed payload)
// ===========================================================================
__global__ void k_zero_deg(int N)
{
    const int i = blockIdx.x * blockDim.x + threadIdx.x;
    if (i < N) deg_buf[i] = 0;
}

__global__ void k_hist(const int* __restrict__ dst, int E)
{
    const int e = blockIdx.x * blockDim.x + threadIdx.x;
    if (e < E) atomicAdd(&deg_buf[dst[e]], 1);
}

__global__ void k_part_sums(int N)
{
    __shared__ int sm[256];
    const int b = blockIdx.x, t = threadIdx.x;
    int s = 0;
#pragma unroll
    for (int k = 0; k < 4; k++) {
        const int i = b * SCAN_CHUNK + k * 256 + t;
        if (i < N) s += deg_buf[i];
    }
    sm[t] = s; __syncthreads();
    for (int off = 128; off > 0; off >>= 1) {
        if (t < off) sm[t] += sm[t + off];
        __syncthreads();
    }
    if (t == 0) part_buf[b] = sm[0];
}

__global__ void k_scan_parts(int nchunks, int N, int E)
{
    __shared__ int sm[128];
    const int t = threadIdx.x;
    const int v = (t < nchunks) ? part_buf[t] : 0;
    sm[t] = v; __syncthreads();
#pragma unroll
    for (int off = 1; off < 128; off <<= 1) {
        const int x = (t >= off) ? sm[t - off] : 0;
        __syncthreads();
        sm[t] += x;
        __syncthreads();
    }
    if (t < nchunks) partoff[t] = sm[t] - v;
    if (t == 0) row_ptr[N] = E;
}

__global__ void k_scan_chunks(int N)
{
    __shared__ int sm[SCAN_CHUNK];
    const int b = blockIdx.x, t = threadIdx.x;
    const int i = b * SCAN_CHUNK + t;
    const int v = (i < N) ? deg_buf[i] : 0;
    sm[t] = v; __syncthreads();
#pragma unroll
    for (int off = 1; off < SCAN_CHUNK; off <<= 1) {
        const int x = (t >= off) ? sm[t - off] : 0;
        __syncthreads();
        sm[t] += x;
        __syncthreads();
    }
    if (i < N) {
        const int ex = sm[t] - v + partoff[b];
        row_ptr[i] = ex;
        cursor[i]  = ex;
    }
}

__global__ void k_scatter(const int* __restrict__ src, const int* __restrict__ dst,
                          const float* __restrict__ ew, int E)
{
    const int e = blockIdx.x * blockDim.x + threadIdx.x;
    if (e >= E) return;
    const int pos = atomicAdd(&cursor[dst[e]], 1);
    int2 pkt;
    pkt.x = src[e];
    pkt.y = __float_as_int(ew[e]);
    edge_sorted[pos] = pkt;                     // single 8 B write
}

// ===========================================================================
// SpMM1 (CSR, F=128) fused with bias+relu+dropout epilogue.
// One warp per dst; lane owns 4 features; 8-edge unroll; packed edge loads.
// ===========================================================================
__global__ void __launch_bounds__(256)
spmm1_fused(const float* __restrict__ b1, int N)
{
    const int d    = (blockIdx.x * blockDim.x + threadIdx.x) >> 5;
    const int lane = threadIdx.x & 31;
    if (d >= N) return;

    const int beg = row_ptr[d];
    const int end = row_ptr[d + 1];

    float4 acc = make_float4(0.f, 0.f, 0.f, 0.f);
    const float* __restrict__ G = g_buf;

    int j = beg;
    for (; j + 8 <= end; j += 8) {
        int2 e[8];
#pragma unroll
        for (int q = 0; q < 8; q++) e[q] = __ldg(&edge_sorted[j + q]);
        float4 v[8];
#pragma unroll
        for (int q = 0; q < 8; q++)
            v[q] = *(const float4*)(G + (size_t)e[q].x * 128 + lane * 4);
#pragma unroll
        for (int q = 0; q < 8; q++) {
            const float w = __int_as_float(e[q].y);
            acc.x += w * v[q].x; acc.y += w * v[q].y;
            acc.z += w * v[q].z; acc.w += w * v[q].w;
        }
    }
    for (; j < end; j++) {
        const int2 e = __ldg(&edge_sorted[j]);
        const float w = __int_as_float(e.y);
        const float4 v = *(const float4*)(G + (size_t)e.x * 128 + lane * 4);
        acc.x += w * v.x; acc.y += w * v.y; acc.z += w * v.z; acc.w += w * v.w;
    }

    // epilogue: h = relu(acc + b1) * mask * 2
    const float4 bv = *(const float4*)(b1 + lane * 4);
    const uint32_t base = (uint32_t)d * 128u + (uint32_t)lane * 4u;

    float4 o;
    float v0 = fmaxf(acc.x + bv.x, 0.f);
    float v1 = fmaxf(acc.y + bv.y, 0.f);
    float v2 = fmaxf(acc.z + bv.z, 0.f);
    float v3 = fmaxf(acc.w + bv.w, 0.f);
    o.x = drop_mask(base + 0u) ? 0.f : v0 * 2.f;
    o.y = drop_mask(base + 1u) ? 0.f : v1 * 2.f;
    o.z = drop_mask(base + 2u) ? 0.f : v2 * 2.f;
    o.w = drop_mask(base + 3u) ? 0.f : v3 * 2.f;
    *(float4*)(h_buf + (size_t)d * 128 + lane * 4) = o;
}

// ===========================================================================
// SpMM2 (CSR, F=64) fused with +b2. One warp per dst; lane owns 2 features.
// ===========================================================================
__global__ void __launch_bounds__(256)
spmm2_fused(const float* __restrict__ b2, float* __restrict__ out, int N)
{
    const int d    = (blockIdx.x * blockDim.x + threadIdx.x) >> 5;
    const int lane = threadIdx.x & 31;
    if (d >= N) return;

    const int beg = row_ptr[d];
    const int end = row_ptr[d + 1];

    float2 acc = make_float2(0.f, 0.f);
    const float* __restrict__ P = p_buf;

    int j = beg;
    for (; j + 8 <= end; j += 8) {
        int2 e[8];
#pragma unroll
        for (int q = 0; q < 8; q++) e[q] = __ldg(&edge_sorted[j + q]);
        float2 v[8];
#pragma unroll
        for (int q = 0; q < 8; q++)
            v[q] = *(const float2*)(P + (size_t)e[q].x * 64 + lane * 2);
#pragma unroll
        for (int q = 0; q < 8; q++) {
            const float w = __int_as_float(e[q].y);
            acc.x += w * v[q].x; acc.y += w * v[q].y;
        }
    }
    for (; j < end; j++) {
        const int2 e = __ldg(&edge_sorted[j]);
        const float w = __int_as_float(e.y);
        const float2 v = *(const float2*)(P + (size_t)e.x * 64 + lane * 2);
        acc.x += w * v.x; acc.y += w * v.y;
    }

    const float2 bv = *(const float2*)(b2 + lane * 2);
    float2 o; o.x = acc.x + bv.x; o.y = acc.y + bv.y;
    *(float2*)(out + (size_t)d * 64 + lane * 2) = o;
}

// ---------------------------------------------------------------------------
// kernel_launch
// inputs: x, edge_weight, W1, b1, W2, b2, src, dst, n_nodes
// ---------------------------------------------------------------------------
extern "C" void kernel_launch(void* const* d_in, const int* in_sizes, int n_in,
                              void* d_out, int out_size)
{
    const float* x   = (const float*)d_in[0];
    const float* ew  = (const float*)d_in[1];
    const float* W1  = (const float*)d_in[2];
    const float* b1  = (const float*)d_in[3];
    const float* W2  = (const float*)d_in[4];
    const float* b2  = (const float*)d_in[5];
    const int*   src = (const int*)d_in[6];
    const int*   dst = (const int*)d_in[7];

    const int N = in_sizes[0] / 128;
    const int E = in_sizes[1];
    float* out = (float*)d_out;

    const int nchunks = (N + SCAN_CHUNK - 1) / SCAN_CHUNK;

    static cudaStream_t s2 = nullptr;
    static cudaEvent_t  ev_fork = nullptr, ev_join = nullptr;
    static bool tried = false;
    if (!tried) {
        tried = true;
        if (cudaStreamCreateWithFlags(&s2, cudaStreamNonBlocking) != cudaSuccess) s2 = nullptr;
        if (s2) {
            cudaEventCreateWithFlags(&ev_fork, cudaEventDisableTiming);
            cudaEventCreateWithFlags(&ev_join, cudaEventDisableTiming);
        }
    }

    cudaStream_t cs = s2 ? s2 : (cudaStream_t)0;

    if (s2) {
        cudaEventRecord(ev_fork, 0);
        cudaStreamWaitEvent(s2, ev_fork, 0);
    }

    // --- CSR build on secondary stream (independent of gemm1) ---
    k_zero_deg   <<<(N + 255) / 256, 256, 0, cs>>>(N);
    k_hist       <<<(E + 255) / 256, 256, 0, cs>>>(dst, E);
    k_part_sums  <<<nchunks, 256, 0, cs>>>(N);
    k_scan_parts <<<1, 128, 0, cs>>>(nchunks, N, E);
    k_scan_chunks<<<nchunks, SCAN_CHUNK, 0, cs>>>(N);
    k_scatter    <<<(E + 255) / 256, 256, 0, cs>>>(src, dst, ew, E);

    if (s2) cudaEventRecord(ev_join, s2);

    // --- gemm1 on main stream, overlapped with CSR build ---
    gemm_k128<128, false><<<(N + 127) / 128, 256>>>(x, W1, N);

    if (s2) cudaStreamWaitEvent((cudaStream_t)0, ev_join, 0);

    // h = relu(spmm(A, g) + b1) * mask * 2
    spmm1_fused<<<(N * 32 + 255) / 256, 256>>>(b1, N);
    // p = h @ W2
    gemm_k128<64, true><<<(N + 127) / 128, 256>>>(nullptr, W2, N);
    // out = spmm(A, p) + b2
    spmm2_fused<<<(N * 32 + 255) / 256, 256>>>(b2, out, N);
}

// round 10
// speedup vs baseline: 1.2809x; 1.0618x over previous
#include <cuda_runtime.h>
#include <cuda_fp16.h>
#include <cstdint>
#include <cstddef>

// ---------------------------------------------------------------------------
// Fixed shapes: N=100000, E=1600000, F 128 -> 128 -> 64
// ---------------------------------------------------------------------------
#define MAX_N 100000
#define MAX_E 1600000
#define SCAN_CHUNK 1024
#define MAX_CHUNKS ((MAX_N + SCAN_CHUNK - 1) / SCAN_CHUNK)   // 98

// Scratch (device BSS — no allocation inside kernel_launch)
__device__ __half g_half[(size_t)MAX_N * 128];   // x @ W1, fp16 (gather-optimized)
__device__ float  h_buf [(size_t)MAX_N * 128];   // relu+bias+dropout(spmm1), fp32
__device__ __half p_half[(size_t)MAX_N * 64];    // h @ W2, fp16 (gather-optimized)

__device__ int   deg_buf   [MAX_N];
__device__ int   row_ptr   [MAX_N + 1];
__device__ int   cursor    [MAX_N];
__device__ int   part_buf  [MAX_CHUNKS];
__device__ int   partoff   [MAX_CHUNKS];
__device__ int2  edge_sorted[MAX_E];             // packed (src, w_bits)

// ---------------------------------------------------------------------------
// Threefry-2x32, key = (0, 42) — bit-exact replica of jax threefry2x32 core
// ---------------------------------------------------------------------------
__device__ __forceinline__ void threefry_0_42(uint32_t x0, uint32_t x1,
                                              uint32_t& o0, uint32_t& o1)
{
    const uint32_t k0 = 0u, k1 = 42u;
    const uint32_t k2 = k0 ^ k1 ^ 0x1BD11BDAu;
    x0 += k0; x1 += k1;
#define TF_R(r) { x0 += x1; x1 = (x1 << (r)) | (x1 >> (32 - (r))); x1 ^= x0; }
    TF_R(13) TF_R(15) TF_R(26) TF_R(6)   x0 += k1; x1 += k2 + 1u;
    TF_R(17) TF_R(29) TF_R(16) TF_R(24)  x0 += k2; x1 += k0 + 2u;
    TF_R(13) TF_R(15) TF_R(26) TF_R(6)   x0 += k0; x1 += k1 + 3u;
    TF_R(17) TF_R(29) TF_R(16) TF_R(24)  x0 += k1; x1 += k2 + 4u;
    TF_R(13) TF_R(15) TF_R(26) TF_R(6)   x0 += k2; x1 += k0 + 5u;
#undef TF_R
    o0 = x0; o1 = x1;
}

__device__ __forceinline__ bool drop_mask(uint32_t i)
{
    uint32_t o0, o1;
    threefry_0_42(0u, i, o0, o1);
    return ((o0 ^ o1) & 0x80000000u) != 0u;   // true = drop (XOR-fold)
}

// ---------------------------------------------------------------------------
// Packed fp32x2 FMA helpers (FFMA2)
// ---------------------------------------------------------------------------
#define FMA2(acc_, a_, b_) \
    asm("fma.rn.f32x2 %0, %1, %2, %0;" : "+l"(acc_) : "l"(a_), "l"(b_))

__device__ __forceinline__ unsigned long long dup2(float a)
{
    unsigned long long r;
    asm("mov.b64 %0, {%1, %1};" : "=l"(r) : "r"(__float_as_uint(a)));
    return r;
}

__device__ __forceinline__ uint32_t pack_half2_from(unsigned long long v64)
{
    // v64 holds two packed fp32; convert to packed half2
    const float lo = __uint_as_float((unsigned)(v64 & 0xffffffffu));
    const float hi = __uint_as_float((unsigned)(v64 >> 32));
    const __half2 h = __floats2half2_rn(lo, hi);
    return *reinterpret_cast<const uint32_t*>(&h);
}

// ===========================================================================
// GEMM1 (FFMA2):  g_half[M,128] = x[M,128] @ W1[128,128], fp16 output
// ===========================================================================
__global__ void __launch_bounds__(256, 2)
gemm1_k128(const float* __restrict__ A, const float* __restrict__ B, int M)
{
    constexpr int BN = 128;
    __shared__ __align__(16) float As[2][16 * 128];
    __shared__ __align__(16) float Bs[2][16 * BN];

    const int tid = threadIdx.x;
    const int tx  = tid & 15;
    const int ty  = tid >> 4;
    const int m0  = blockIdx.x * 128;
    const int lr  = tid >> 2;
    const int lc  = tid & 3;

    unsigned long long acc[8][4];
#pragma unroll
    for (int r = 0; r < 8; r++)
#pragma unroll
        for (int j = 0; j < 4; j++) acc[r][j] = 0ull;

    auto loadTiles = [&](int buf, int kk) {
#pragma unroll
        for (int rr = 0; rr < 2; rr++) {
            int row = m0 + lr + rr * 64;
            if (row > M - 1) row = M - 1;
            const float4 v = *(const float4*)(A + (size_t)row * 128 + kk + lc * 4);
            float* d = &As[buf][0];
            const int mi = lr + rr * 64;
            d[(lc * 4 + 0) * 128 + mi] = v.x;
            d[(lc * 4 + 1) * 128 + mi] = v.y;
            d[(lc * 4 + 2) * 128 + mi] = v.z;
            d[(lc * 4 + 3) * 128 + mi] = v.w;
        }
#pragma unroll
        for (int i = 0; i < 2; i++) {
            const int idx = (i * 256 + tid) * 4;
            *(float4*)&Bs[buf][idx] = *(const float4*)(B + kk * BN + idx);
        }
    };

    loadTiles(0, 0);
    __syncthreads();

#pragma unroll 1
    for (int kk = 0; kk < 128; kk += 16) {
        const int cur = (kk >> 4) & 1;
        if (kk + 16 < 128) loadTiles(cur ^ 1, kk + 16);
#pragma unroll
        for (int k = 0; k < 16; k++) {
            const float4 a0 = *(const float4*)&As[cur][k * 128 + ty * 4];
            const float4 a1 = *(const float4*)&As[cur][k * 128 + ty * 4 + 64];
            unsigned long long a2[8];
            a2[0] = dup2(a0.x); a2[1] = dup2(a0.y);
            a2[2] = dup2(a0.z); a2[3] = dup2(a0.w);
            a2[4] = dup2(a1.x); a2[5] = dup2(a1.y);
            a2[6] = dup2(a1.z); a2[7] = dup2(a1.w);
#pragma unroll
            for (int g = 0; g < 2; g++) {
                const double2 b = *(const double2*)&Bs[cur][k * BN + tx * 4 + g * 64];
                const unsigned long long bl = __double_as_longlong(b.x);
                const unsigned long long bh = __double_as_longlong(b.y);
#pragma unroll
                for (int r = 0; r < 8; r++) {
                    FMA2(acc[r][2 * g + 0], a2[r], bl);
                    FMA2(acc[r][2 * g + 1], a2[r], bh);
                }
            }
        }
        __syncthreads();
    }

#pragma unroll
    for (int r = 0; r < 8; r++) {
        const int row = m0 + ty * 4 + (r >> 2) * 64 + (r & 3);
        if (row < M) {
#pragma unroll
            for (int g = 0; g < 2; g++) {
                uint2 o;
                o.x = pack_half2_from(acc[r][2 * g + 0]);
                o.y = pack_half2_from(acc[r][2 * g + 1]);
                *(uint2*)(g_half + (size_t)row * 128 + tx * 4 + g * 64) = o;
            }
        }
    }
}

// ===========================================================================
// GEMM2 (FFMA2):  p_half[M,64] = h[M,128] @ W2[128,64], fp16 output
// ===========================================================================
__global__ void __launch_bounds__(256, 2)
gemm2_k128(const float* __restrict__ B, int M)
{
    constexpr int BN = 64;
    const float* __restrict__ A = h_buf;

    __shared__ __align__(16) float As[2][16 * 128];
    __shared__ __align__(16) float Bs[2][16 * BN];

    const int tid = threadIdx.x;
    const int tx  = tid & 15;
    const int ty  = tid >> 4;
    const int m0  = blockIdx.x * 128;
    const int lr  = tid >> 2;
    const int lc  = tid & 3;

    unsigned long long acc[8][2];
#pragma unroll
    for (int r = 0; r < 8; r++) { acc[r][0] = 0ull; acc[r][1] = 0ull; }

    auto loadTiles = [&](int buf, int kk) {
#pragma unroll
        for (int rr = 0; rr < 2; rr++) {
            int row = m0 + lr + rr * 64;
            if (row > M - 1) row = M - 1;
            const float4 v = *(const float4*)(A + (size_t)row * 128 + kk + lc * 4);
            float* d = &As[buf][0];
            const int mi = lr + rr * 64;
            d[(lc * 4 + 0) * 128 + mi] = v.x;
            d[(lc * 4 + 1) * 128 + mi] = v.y;
            d[(lc * 4 + 2) * 128 + mi] = v.z;
            d[(lc * 4 + 3) * 128 + mi] = v.w;
        }
        {
            const int idx = tid * 4;
            if (idx < 16 * BN)
                *(float4*)&Bs[buf][idx] = *(const float4*)(B + kk * BN + idx);
        }
    };

    loadTiles(0, 0);
    __syncthreads();

#pragma unroll 1
    for (int kk = 0; kk < 128; kk += 16) {
        const int cur = (kk >> 4) & 1;
        if (kk + 16 < 128) loadTiles(cur ^ 1, kk + 16);
#pragma unroll
        for (int k = 0; k < 16; k++) {
            const float4 a0 = *(const float4*)&As[cur][k * 128 + ty * 4];
            const float4 a1 = *(const float4*)&As[cur][k * 128 + ty * 4 + 64];
            unsigned long long a2[8];
            a2[0] = dup2(a0.x); a2[1] = dup2(a0.y);
            a2[2] = dup2(a0.z); a2[3] = dup2(a0.w);
            a2[4] = dup2(a1.x); a2[5] = dup2(a1.y);
            a2[6] = dup2(a1.z); a2[7] = dup2(a1.w);
            const double2 b = *(const double2*)&Bs[cur][k * BN + tx * 4];
            const unsigned long long bl = __double_as_longlong(b.x);
            const unsigned long long bh = __double_as_longlong(b.y);
#pragma unroll
            for (int r = 0; r < 8; r++) {
                FMA2(acc[r][0], a2[r], bl);
                FMA2(acc[r][1], a2[r], bh);
            }
        }
        __syncthreads();
    }

#pragma unroll
    for (int r = 0; r < 8; r++) {
        const int row = m0 + ty * 4 + (r >> 2) * 64 + (r & 3);
        if (row < M) {
            uint2 o;
            o.x = pack_half2_from(acc[r][0]);
            o.y = pack_half2_from(acc[r][1]);
            *(uint2*)(p_half + (size_t)row * 64 + tx * 4) = o;
        }
    }
}

// ===========================================================================
// CSR build: deg -> scan -> scatter (packed payload)
// ===========================================================================
__global__ void k_zero_deg(int N)
{
    const int i = blockIdx.x * blockDim.x + threadIdx.x;
    if (i < N) deg_buf[i] = 0;
}

__global__ void k_hist(const int* __restrict__ dst, int E)
{
    const int e = blockIdx.x * blockDim.x + threadIdx.x;
    if (e < E) atomicAdd(&deg_buf[dst[e]], 1);
}

__global__ void k_part_sums(int N)
{
    __shared__ int sm[256];
    const int b = blockIdx.x, t = threadIdx.x;
    int s = 0;
#pragma unroll
    for (int k = 0; k < 4; k++) {
        const int i = b * SCAN_CHUNK + k * 256 + t;
        if (i < N) s += deg_buf[i];
    }
    sm[t] = s; __syncthreads();
    for (int off = 128; off > 0; off >>= 1) {
        if (t < off) sm[t] += sm[t + off];
        __syncthreads();
    }
    if (t == 0) part_buf[b] = sm[0];
}

__global__ void k_scan_parts(int nchunks, int N, int E)
{
    __shared__ int sm[128];
    const int t = threadIdx.x;
    const int v = (t < nchunks) ? part_buf[t] : 0;
    sm[t] = v; __syncthreads();
#pragma unroll
    for (int off = 1; off < 128; off <<= 1) {
        const int x = (t >= off) ? sm[t - off] : 0;
        __syncthreads();
        sm[t] += x;
        __syncthreads();
    }
    if (t < nchunks) partoff[t] = sm[t] - v;
    if (t == 0) row_ptr[N] = E;
}

__global__ void k_scan_chunks(int N)
{
    __shared__ int sm[SCAN_CHUNK];
    const int b = blockIdx.x, t = threadIdx.x;
    const int i = b * SCAN_CHUNK + t;
    const int v = (i < N) ? deg_buf[i] : 0;
    sm[t] = v; __syncthreads();
#pragma unroll
    for (int off = 1; off < SCAN_CHUNK; off <<= 1) {
        const int x = (t >= off) ? sm[t - off] : 0;
        __syncthreads();
        sm[t] += x;
        __syncthreads();
    }
    if (i < N) {
        const int ex = sm[t] - v + partoff[b];
        row_ptr[i] = ex;
        cursor[i]  = ex;
    }
}

__global__ void k_scatter(const int* __restrict__ src, const int* __restrict__ dst,
                          const float* __restrict__ ew, int E)
{
    const int e = blockIdx.x * blockDim.x + threadIdx.x;
    if (e >= E) return;
    const int pos = atomicAdd(&cursor[dst[e]], 1);
    int2 pkt;
    pkt.x = src[e];
    pkt.y = __float_as_int(ew[e]);
    edge_sorted[pos] = pkt;
}

// ===========================================================================
// SpMM1 (CSR, F=128, fp16 gather) fused with bias+relu+dropout epilogue.
// One warp per dst; lane owns 4 features (half4 = 8 B gather); fp32 accum.
// ===========================================================================
__global__ void __launch_bounds__(256)
spmm1_fused(const float* __restrict__ b1, int N)
{
    const int d    = (blockIdx.x * blockDim.x + threadIdx.x) >> 5;
    const int lane = threadIdx.x & 31;
    if (d >= N) return;

    const int beg = row_ptr[d];
    const int end = row_ptr[d + 1];

    float4 acc = make_float4(0.f, 0.f, 0.f, 0.f);
    const __half* __restrict__ G = g_half;

    int j = beg;
    for (; j + 8 <= end; j += 8) {
        int2 e[8];
#pragma unroll
        for (int q = 0; q < 8; q++) e[q] = __ldg(&edge_sorted[j + q]);
        uint2 gv[8];
#pragma unroll
        for (int q = 0; q < 8; q++)
            gv[q] = *(const uint2*)(G + (size_t)e[q].x * 128 + lane * 4);
#pragma unroll
        for (int q = 0; q < 8; q++) {
            const float w = __int_as_float(e[q].y);
            const float2 f0 = __half22float2(*reinterpret_cast<const __half2*>(&gv[q].x));
            const float2 f1 = __half22float2(*reinterpret_cast<const __half2*>(&gv[q].y));
            acc.x += w * f0.x; acc.y += w * f0.y;
            acc.z += w * f1.x; acc.w += w * f1.y;
        }
    }
    for (; j < end; j++) {
        const int2 e = __ldg(&edge_sorted[j]);
        const float w = __int_as_float(e.y);
        const uint2 gv = *(const uint2*)(G + (size_t)e.x * 128 + lane * 4);
        const float2 f0 = __half22float2(*reinterpret_cast<const __half2*>(&gv.x));
        const float2 f1 = __half22float2(*reinterpret_cast<const __half2*>(&gv.y));
        acc.x += w * f0.x; acc.y += w * f0.y;
        acc.z += w * f1.x; acc.w += w * f1.y;
    }

    // epilogue: h = relu(acc + b1) * mask * 2   (fp32 output)
    const float4 bv = *(const float4*)(b1 + lane * 4);
    const uint32_t base = (uint32_t)d * 128u + (uint32_t)lane * 4u;

    float4 o;
    float v0 = fmaxf(acc.x + bv.x, 0.f);
    float v1 = fmaxf(acc.y + bv.y, 0.f);
    float v2 = fmaxf(acc.z + bv.z, 0.f);
    float v3 = fmaxf(acc.w + bv.w, 0.f);
    o.x = drop_mask(base + 0u) ? 0.f : v0 * 2.f;
    o.y = drop_mask(base + 1u) ? 0.f : v1 * 2.f;
    o.z = drop_mask(base + 2u) ? 0.f : v2 * 2.f;
    o.w = drop_mask(base + 3u) ? 0.f : v3 * 2.f;
    *(float4*)(h_buf + (size_t)d * 128 + lane * 4) = o;
}

// ===========================================================================
// SpMM2 (CSR, F=64, fp16 gather) fused with +b2. Lane owns 2 features.
// ===========================================================================
__global__ void __launch_bounds__(256)
spmm2_fused(const float* __restrict__ b2, float* __restrict__ out, int N)
{
    const int d    = (blockIdx.x * blockDim.x + threadIdx.x) >> 5;
    const int lane = threadIdx.x & 31;
    if (d >= N) return;

    const int beg = row_ptr[d];
    const int end = row_ptr[d + 1];

    float2 acc = make_float2(0.f, 0.f);
    const __half* __restrict__ P = p_half;

    int j = beg;
    for (; j + 8 <= end; j += 8) {
        int2 e[8];
#pragma unroll
        for (int q = 0; q < 8; q++) e[q] = __ldg(&edge_sorted[j + q]);
        __half2 pv[8];
#pragma unroll
        for (int q = 0; q < 8; q++)
            pv[q] = *(const __half2*)(P + (size_t)e[q].x * 64 + lane * 2);
#pragma unroll
        for (int q = 0; q < 8; q++) {
            const float w = __int_as_float(e[q].y);
            const float2 f = __half22float2(pv[q]);
            acc.x += w * f.x; acc.y += w * f.y;
        }
    }
    for (; j < end; j++) {
        const int2 e = __ldg(&edge_sorted[j]);
        const float w = __int_as_float(e.y);
        const float2 f = __half22float2(*(const __half2*)(P + (size_t)e.x * 64 + lane * 2));
        acc.x += w * f.x; acc.y += w * f.y;
    }

    const float2 bv = *(const float2*)(b2 + lane * 2);
    float2 o; o.x = acc.x + bv.x; o.y = acc.y + bv.y;
    *(float2*)(out + (size_t)d * 64 + lane * 2) = o;
}

// ---------------------------------------------------------------------------
// kernel_launch
// inputs: x, edge_weight, W1, b1, W2, b2, src, dst, n_nodes
// ---------------------------------------------------------------------------
extern "C" void kernel_launch(void* const* d_in, const int* in_sizes, int n_in,
                              void* d_out, int out_size)
{
    const float* x   = (const float*)d_in[0];
    const float* ew  = (const float*)d_in[1];
    const float* W1  = (const float*)d_in[2];
    const float* b1  = (const float*)d_in[3];
    const float* W2  = (const float*)d_in[4];
    const float* b2  = (const float*)d_in[5];
    const int*   src = (const int*)d_in[6];
    const int*   dst = (const int*)d_in[7];

    const int N = in_sizes[0] / 128;
    const int E = in_sizes[1];
    float* out = (float*)d_out;

    const int nchunks = (N + SCAN_CHUNK - 1) / SCAN_CHUNK;

    static cudaStream_t s2 = nullptr;
    static cudaEvent_t  ev_fork = nullptr, ev_join = nullptr;
    static bool tried = false;
    if (!tried) {
        tried = true;
        if (cudaStreamCreateWithFlags(&s2, cudaStreamNonBlocking) != cudaSuccess) s2 = nullptr;
        if (s2) {
            cudaEventCreateWithFlags(&ev_fork, cudaEventDisableTiming);
            cudaEventCreateWithFlags(&ev_join, cudaEventDisableTiming);
        }
    }

    cudaStream_t cs = s2 ? s2 : (cudaStream_t)0;

    if (s2) {
        cudaEventRecord(ev_fork, 0);
        cudaStreamWaitEvent(s2, ev_fork, 0);
    }

    // --- CSR build on secondary stream (independent of gemm1) ---
    k_zero_deg   <<<(N + 255) / 256, 256, 0, cs>>>(N);
    k_hist       <<<(E + 255) / 256, 256, 0, cs>>>(dst, E);
    k_part_sums  <<<nchunks, 256, 0, cs>>>(N);
    k_scan_parts <<<1, 128, 0, cs>>>(nchunks, N, E);
    k_scan_chunks<<<nchunks, SCAN_CHUNK, 0, cs>>>(N);
    k_scatter    <<<(E + 255) / 256, 256, 0, cs>>>(src, dst, ew, E);

    if (s2) cudaEventRecord(ev_join, s2);

    // --- gemm1 on main stream, overlapped with CSR build ---
    gemm1_k128<<<(N + 127) / 128, 256>>>(x, W1, N);

    if (s2) cudaStreamWaitEvent((cudaStream_t)0, ev_join, 0);

    // h = relu(spmm(A, g) + b1) * mask * 2    (fp16 gather, fp32 accum)
    spmm1_fused<<<(N * 32 + 255) / 256, 256>>>(b1, N);
    // p = h @ W2                               (fp16 output)
    gemm2_k128<<<(N + 127) / 128, 256>>>(W2, N);
    // out = spmm(A, p) + b2                    (fp16 gather, fp32 accum)
    spmm2_fused<<<(N * 32 + 255) / 256, 256>>>(b2, out, N);
}